// round 3
// baseline (speedup 1.0000x reference)
#include <cuda_runtime.h>

#define T_LEN 2048
#define BATCH 8
#define EMBED 1024
#define NHEADS 16
#define HDIM 64
#define BH 128            // BATCH * NHEADS
#define MROWS 16384       // T_LEN * BATCH
#define NQKV 3072         // 3 * EMBED
#define QK_LD 65
#define S_LD 129

// Scratch (allowed: __device__ globals, no dynamic allocation)
__device__ float g_qkv[(size_t)MROWS * NQKV];   // [T*B, 3E]
__device__ float g_ws[(size_t)MROWS * EMBED];   // [B, T, E]

// ---------------------------------------------------------------------------
// C[m][n] = sum_k A[m][k] * B[n][k] + bias[n]
// 128x128 block tile, BK=8, 256 threads, 8x8 per thread.
// M, N, K all multiples of 128/128/8 for this problem -> no bounds checks.
// ---------------------------------------------------------------------------
__device__ __forceinline__ void sgemm_128x128(
    const float* __restrict__ A, const float* __restrict__ B,
    const float* __restrict__ bias, float* __restrict__ C,
    int N, int K)
{
    __shared__ float As[8][128];
    __shared__ float Bs[8][128];
    const int tid = threadIdx.x;
    const int bm = blockIdx.y << 7;
    const int bn = blockIdx.x << 7;
    const int lr = tid >> 1;          // row within tile (0..127)
    const int lc = (tid & 1) << 2;    // k offset (0 or 4)
    const float* Ap = A + (size_t)(bm + lr) * K + lc;
    const float* Bp = B + (size_t)(bn + lr) * K + lc;
    const int tx = tid & 15;
    const int ty = tid >> 4;

    float acc[8][8];
#pragma unroll
    for (int i = 0; i < 8; i++)
#pragma unroll
        for (int j = 0; j < 8; j++) acc[i][j] = 0.0f;

    for (int k0 = 0; k0 < K; k0 += 8) {
        float4 av = *(const float4*)(Ap + k0);
        float4 bv = *(const float4*)(Bp + k0);
        As[lc + 0][lr] = av.x; As[lc + 1][lr] = av.y;
        As[lc + 2][lr] = av.z; As[lc + 3][lr] = av.w;
        Bs[lc + 0][lr] = bv.x; Bs[lc + 1][lr] = bv.y;
        Bs[lc + 2][lr] = bv.z; Bs[lc + 3][lr] = bv.w;
        __syncthreads();
#pragma unroll
        for (int k = 0; k < 8; k++) {
            float a_frag[8], b_frag[8];
            *(float4*)&a_frag[0] = *(const float4*)&As[k][(ty << 3)];
            *(float4*)&a_frag[4] = *(const float4*)&As[k][(ty << 3) + 4];
            *(float4*)&b_frag[0] = *(const float4*)&Bs[k][(tx << 3)];
            *(float4*)&b_frag[4] = *(const float4*)&Bs[k][(tx << 3) + 4];
#pragma unroll
            for (int i = 0; i < 8; i++)
#pragma unroll
                for (int j = 0; j < 8; j++)
                    acc[i][j] = fmaf(a_frag[i], b_frag[j], acc[i][j]);
        }
        __syncthreads();
    }
#pragma unroll
    for (int i = 0; i < 8; i++) {
        float* Crow = C + (size_t)(bm + (ty << 3) + i) * N + bn + (tx << 3);
        const float* brow = bias + bn + (tx << 3);
#pragma unroll
        for (int j = 0; j < 8; j += 4) {
            float4 o;
            o.x = acc[i][j + 0] + brow[j + 0];
            o.y = acc[i][j + 1] + brow[j + 1];
            o.z = acc[i][j + 2] + brow[j + 2];
            o.w = acc[i][j + 3] + brow[j + 3];
            *(float4*)(Crow + j) = o;
        }
    }
}

__global__ __launch_bounds__(256) void gemm_qkv_kernel(
    const float* __restrict__ X, const float* __restrict__ W,
    const float* __restrict__ bias)
{
    sgemm_128x128(X, W, bias, g_qkv, NQKV, EMBED);
}

__global__ __launch_bounds__(256) void gemm_out_kernel(
    const float* __restrict__ W, const float* __restrict__ bias,
    float* __restrict__ C)
{
    sgemm_128x128(g_ws, W, bias, C, EMBED, EMBED);
}

// ---------------------------------------------------------------------------
// Per-t attention: one block per t (2048 blocks, 256 threads).
// Rows a = b*16 + h, a in [0,128). q/k L2 norm applied as post-scale on the
// raw dot product: S[i][j] = (q_raw[i].k_raw[j]) * invq[i] * invk[j] / 8.
// ---------------------------------------------------------------------------
__global__ __launch_bounds__(256) void attn_kernel()
{
    extern __shared__ float smem[];
    float* qs   = smem;                    // 128 x 65
    float* ks   = qs + BH * QK_LD;         // 128 x 65
    float* vs   = ks + BH * QK_LD;         // 128 x 65
    float* Ss   = vs + BH * QK_LD;         // 128 x 129
    float* invq = Ss + BH * S_LD;          // 128
    float* invk = invq + BH;               // 128

    const int t = blockIdx.x;
    const int tid = threadIdx.x;

    // Load q,k,v tiles (coalesced float4 global reads)
    for (int idx = tid; idx < BH * (HDIM / 4); idx += 256) {
        int a  = idx >> 4;                 // row 0..127
        int d4 = (idx & 15) << 2;          // col 0,4,..,60
        int b = a >> 4, h = a & 15;
        const float* base = g_qkv + (size_t)(t * BATCH + b) * NQKV + h * HDIM + d4;
        float4 qv = *(const float4*)(base);
        float4 kv = *(const float4*)(base + EMBED);
        float4 vv = *(const float4*)(base + 2 * EMBED);
        float* qd = qs + a * QK_LD + d4;
        qd[0] = qv.x; qd[1] = qv.y; qd[2] = qv.z; qd[3] = qv.w;
        float* kd = ks + a * QK_LD + d4;
        kd[0] = kv.x; kd[1] = kv.y; kd[2] = kv.z; kd[3] = kv.w;
        float* vd = vs + a * QK_LD + d4;
        vd[0] = vv.x; vd[1] = vv.y; vd[2] = vv.z; vd[3] = vv.w;
    }
    __syncthreads();

    // Row norms (128 threads for q, 128 for k)
    if (tid < BH) {
        const float* r = qs + tid * QK_LD;
        float s = 0.0f;
#pragma unroll
        for (int d = 0; d < HDIM; d++) s = fmaf(r[d], r[d], s);
        invq[tid] = rsqrtf(s);
    } else {
        const float* r = ks + (tid - BH) * QK_LD;
        float s = 0.0f;
#pragma unroll
        for (int d = 0; d < HDIM; d++) s = fmaf(r[d], r[d], s);
        invk[tid - BH] = rsqrtf(s);
    }
    __syncthreads();

    const int tx = tid & 15, ty = tid >> 4;

    // S = q_raw @ k_raw^T, then scale by invq*invk/8
    {
        float acc[8][8];
#pragma unroll
        for (int i = 0; i < 8; i++)
#pragma unroll
            for (int j = 0; j < 8; j++) acc[i][j] = 0.0f;

#pragma unroll 8
        for (int k = 0; k < HDIM; k++) {
            float a_frag[8], b_frag[8];
#pragma unroll
            for (int i = 0; i < 8; i++) a_frag[i] = qs[((ty << 3) + i) * QK_LD + k];
#pragma unroll
            for (int j = 0; j < 8; j++) b_frag[j] = ks[((tx << 3) + j) * QK_LD + k];
#pragma unroll
            for (int i = 0; i < 8; i++)
#pragma unroll
                for (int j = 0; j < 8; j++)
                    acc[i][j] = fmaf(a_frag[i], b_frag[j], acc[i][j]);
        }
#pragma unroll
        for (int i = 0; i < 8; i++) {
            float si = invq[(ty << 3) + i] * 0.125f;
            float* srow = Ss + ((ty << 3) + i) * S_LD + (tx << 3);
#pragma unroll
            for (int j = 0; j < 8; j++)
                srow[j] = acc[i][j] * si * invk[(tx << 3) + j];
        }
    }
    __syncthreads();

    // Softmax over 128 cols; one warp handles 16 rows, 4 cols per lane
    {
        const int warp = tid >> 5, lane = tid & 31;
        for (int r = warp * 16; r < warp * 16 + 16; r++) {
            float* row = Ss + r * S_LD;
            float v0 = row[lane], v1 = row[lane + 32];
            float v2 = row[lane + 64], v3 = row[lane + 96];
            float m = fmaxf(fmaxf(v0, v1), fmaxf(v2, v3));
#pragma unroll
            for (int o = 16; o > 0; o >>= 1)
                m = fmaxf(m, __shfl_xor_sync(0xffffffffu, m, o));
            v0 = __expf(v0 - m); v1 = __expf(v1 - m);
            v2 = __expf(v2 - m); v3 = __expf(v3 - m);
            float s = v0 + v1 + v2 + v3;
#pragma unroll
            for (int o = 16; o > 0; o >>= 1)
                s += __shfl_xor_sync(0xffffffffu, s, o);
            float inv = 1.0f / s;
            row[lane] = v0 * inv; row[lane + 32] = v1 * inv;
            row[lane + 64] = v2 * inv; row[lane + 96] = v3 * inv;
        }
    }
    __syncthreads();

    // ws = P @ V : thread computes rows ty*8..+7, cols tx*4..+3
    {
        float o[8][4];
#pragma unroll
        for (int i = 0; i < 8; i++)
#pragma unroll
            for (int c = 0; c < 4; c++) o[i][c] = 0.0f;

#pragma unroll 4
        for (int j = 0; j < BH; j++) {
            const float* vrow = vs + j * QK_LD + (tx << 2);
            float vv0 = vrow[0], vv1 = vrow[1], vv2 = vrow[2], vv3 = vrow[3];
#pragma unroll
            for (int i = 0; i < 8; i++) {
                float p = Ss[((ty << 3) + i) * S_LD + j];
                o[i][0] = fmaf(p, vv0, o[i][0]);
                o[i][1] = fmaf(p, vv1, o[i][1]);
                o[i][2] = fmaf(p, vv2, o[i][2]);
                o[i][3] = fmaf(p, vv3, o[i][3]);
            }
        }
        // Store transposed to [B, T, E]
#pragma unroll
        for (int i = 0; i < 8; i++) {
            int a = (ty << 3) + i;
            int b = a >> 4, h = a & 15;
            float* dst = g_ws + ((size_t)b * T_LEN + t) * EMBED + h * HDIM + (tx << 2);
            float4 ov = make_float4(o[i][0], o[i][1], o[i][2], o[i][3]);
            *(float4*)dst = ov;
        }
    }
}

// ---------------------------------------------------------------------------
extern "C" void kernel_launch(void* const* d_in, const int* in_sizes, int n_in,
                              void* d_out, int out_size)
{
    const float* query = (const float*)d_in[0];
    // d_in[1] = key, d_in[2] = value: unused by the reference math
    const float* w_qkv = (const float*)d_in[3];
    const float* b_qkv = (const float*)d_in[4];
    const float* w_out = (const float*)d_in[5];
    const float* b_out = (const float*)d_in[6];
    float* out = (float*)d_out;

    const int attn_smem = (3 * BH * QK_LD + BH * S_LD + 2 * BH) * (int)sizeof(float);
    cudaFuncSetAttribute(attn_kernel,
                         cudaFuncAttributeMaxDynamicSharedMemorySize, attn_smem);

    gemm_qkv_kernel<<<dim3(NQKV / 128, MROWS / 128), 256>>>(query, w_qkv, b_qkv);
    attn_kernel<<<T_LEN, 256, attn_smem>>>();
    gemm_out_kernel<<<dim3(EMBED / 128, MROWS / 128), 256>>>(w_out, b_out, out);
}

// round 4
// speedup vs baseline: 2.6762x; 2.6762x over previous
#include <cuda_runtime.h>
#include <cstdint>

#define T_LEN 2048
#define BATCH 8
#define EMBED 1024
#define NHEADS 16
#define HDIM 64
#define BH 128            // BATCH * NHEADS
#define MROWS 16384       // T_LEN * BATCH
#define NQKV 3072         // 3 * EMBED
#define QK_LD 65
#define S_LD 129

#define BK 32
#define TLD 36            // smem leading dim (floats) for A/B tiles
#define STAGES 3
#define TILE_FLOATS (128 * TLD)
#define GEMM_SMEM (STAGES * 2 * TILE_FLOATS * 4)

// Scratch (allowed: __device__ globals, no dynamic allocation)
__device__ float g_qkv[(size_t)MROWS * NQKV];   // [T*B, 3E]
__device__ float g_ws[(size_t)MROWS * EMBED];   // [B, T, E]

// ---------------------------------------------------------------------------
// tf32 tensor-core GEMM: C[m][n] = sum_k A[m][k]*B[n][k] + bias[n]
// 128x128 tile, BK=32, 256 threads, 8 warps (2x4), warp tile 64x32.
// mma.sync.m16n8k8 tf32 with fp32 accumulate; cvt.rna for round-to-nearest.
// M,N multiples of 128; K multiple of 32.
// ---------------------------------------------------------------------------
__global__ __launch_bounds__(256, 1) void gemm_tf32_kernel(
    const float* __restrict__ A, const float* __restrict__ B,
    const float* __restrict__ bias, float* __restrict__ C,
    int N, int K)
{
    extern __shared__ float sm[];
    const int tid  = threadIdx.x;
    const int lane = tid & 31;
    const int warp = tid >> 5;
    const int wm   = warp >> 2;        // 0..1
    const int wn   = warp & 3;         // 0..3
    const int bm   = blockIdx.y << 7;
    const int bn   = blockIdx.x << 7;

    // global load coords: idx = tid + i*256; row = idx>>3, kchunk = idx&7
    const int lrow = tid >> 3;         // 0..31
    const int lkc  = tid & 7;          // 0..7 (float4 chunks)
    const float* gA = A + (size_t)(bm + lrow) * K + lkc * 4;
    const float* gB = B + (size_t)(bn + lrow) * K + lkc * 4;

    float c[4][4][4];
#pragma unroll
    for (int mf = 0; mf < 4; mf++)
#pragma unroll
        for (int nf = 0; nf < 4; nf++)
#pragma unroll
            for (int r = 0; r < 4; r++) c[mf][nf][r] = 0.0f;

    const int ntiles = K >> 5;

#define LOAD_TILE(s, k0) do {                                                  \
    float* As_ = sm + (s) * (2 * TILE_FLOATS);                                 \
    float* Bs_ = As_ + TILE_FLOATS;                                            \
    _Pragma("unroll")                                                          \
    for (int i_ = 0; i_ < 4; i_++) {                                           \
        uint32_t sa_ = (uint32_t)__cvta_generic_to_shared(                     \
            As_ + (lrow + i_ * 32) * TLD + lkc * 4);                           \
        asm volatile("cp.async.cg.shared.global [%0], [%1], 16;\n"             \
                     :: "r"(sa_), "l"(gA + (size_t)(i_ * 32) * K + (k0)));     \
        uint32_t sb_ = (uint32_t)__cvta_generic_to_shared(                     \
            Bs_ + (lrow + i_ * 32) * TLD + lkc * 4);                           \
        asm volatile("cp.async.cg.shared.global [%0], [%1], 16;\n"             \
                     :: "r"(sb_), "l"(gB + (size_t)(i_ * 32) * K + (k0)));     \
    }                                                                          \
} while (0)

    // prologue: fill STAGES-1 stages
#pragma unroll
    for (int s = 0; s < STAGES - 1; s++) {
        if (s < ntiles) LOAD_TILE(s, s * BK);
        asm volatile("cp.async.commit_group;\n");
    }
    asm volatile("cp.async.wait_group %0;\n" :: "n"(STAGES - 2));
    __syncthreads();

    for (int kt = 0; kt < ntiles; kt++) {
        // prefetch (target stage was fully consumed before last __syncthreads)
        int pf = kt + STAGES - 1;
        if (pf < ntiles) LOAD_TILE(pf % STAGES, pf * BK);
        asm volatile("cp.async.commit_group;\n");

        const float* As = sm + (kt % STAGES) * (2 * TILE_FLOATS);
        const float* Bs = As + TILE_FLOATS;

#pragma unroll
        for (int k8 = 0; k8 < 4; k8++) {
            uint32_t afr[4][4];
#pragma unroll
            for (int mf = 0; mf < 4; mf++) {
                // ldmatrix x4: mats = {rows0-7 k0-3, rows8-15 k0-3,
                //                      rows0-7 k4-7, rows8-15 k4-7}
                uint32_t addr = (uint32_t)__cvta_generic_to_shared(
                    As + (wm * 64 + mf * 16 + (lane & 15)) * TLD
                       + k8 * 8 + (lane >> 4) * 4);
                asm volatile(
                    "ldmatrix.sync.aligned.m8n8.x4.b16 {%0,%1,%2,%3}, [%4];\n"
                    : "=r"(afr[mf][0]), "=r"(afr[mf][1]),
                      "=r"(afr[mf][2]), "=r"(afr[mf][3])
                    : "r"(addr));
            }
            uint32_t bfr[4][2];
#pragma unroll
            for (int nf = 0; nf < 4; nf++) {
                float b0 = Bs[(wn * 32 + nf * 8 + (lane >> 2)) * TLD
                              + k8 * 8 + (lane & 3)];
                float b1 = Bs[(wn * 32 + nf * 8 + (lane >> 2)) * TLD
                              + k8 * 8 + (lane & 3) + 4];
                asm("cvt.rna.tf32.f32 %0, %1;\n" : "=r"(bfr[nf][0]) : "f"(b0));
                asm("cvt.rna.tf32.f32 %0, %1;\n" : "=r"(bfr[nf][1]) : "f"(b1));
            }
#pragma unroll
            for (int mf = 0; mf < 4; mf++)
#pragma unroll
                for (int r = 0; r < 4; r++) {
                    float fa = __uint_as_float(afr[mf][r]);
                    asm("cvt.rna.tf32.f32 %0, %1;\n"
                        : "=r"(afr[mf][r]) : "f"(fa));
                }
#pragma unroll
            for (int mf = 0; mf < 4; mf++)
#pragma unroll
                for (int nf = 0; nf < 4; nf++) {
                    asm volatile(
                        "mma.sync.aligned.m16n8k8.row.col.f32.tf32.tf32.f32 "
                        "{%0,%1,%2,%3}, {%4,%5,%6,%7}, {%8,%9}, {%0,%1,%2,%3};\n"
                        : "+f"(c[mf][nf][0]), "+f"(c[mf][nf][1]),
                          "+f"(c[mf][nf][2]), "+f"(c[mf][nf][3])
                        : "r"(afr[mf][0]), "r"(afr[mf][1]),
                          "r"(afr[mf][2]), "r"(afr[mf][3]),
                          "r"(bfr[nf][0]), "r"(bfr[nf][1]));
                }
        }

        asm volatile("cp.async.wait_group %0;\n" :: "n"(STAGES - 2));
        __syncthreads();
    }

    // epilogue
#pragma unroll
    for (int mf = 0; mf < 4; mf++) {
        int r0 = bm + wm * 64 + mf * 16 + (lane >> 2);
#pragma unroll
        for (int nf = 0; nf < 4; nf++) {
            int col = bn + wn * 32 + nf * 8 + ((lane & 3) << 1);
            float2 bv = *(const float2*)(bias + col);
            float2 o0 = make_float2(c[mf][nf][0] + bv.x, c[mf][nf][1] + bv.y);
            float2 o1 = make_float2(c[mf][nf][2] + bv.x, c[mf][nf][3] + bv.y);
            *(float2*)(C + (size_t)r0 * N + col) = o0;
            *(float2*)(C + (size_t)(r0 + 8) * N + col) = o1;
        }
    }
#undef LOAD_TILE
}

// ---------------------------------------------------------------------------
// Per-t attention: one block per t (2048 blocks, 256 threads). fp32 exact.
// S[i][j] = (q_raw[i].k_raw[j]) * invq[i] * invk[j] / 8, softmax, P@V.
// ---------------------------------------------------------------------------
__global__ __launch_bounds__(256) void attn_kernel()
{
    extern __shared__ float smem[];
    float* qs   = smem;                    // 128 x 65
    float* ks   = qs + BH * QK_LD;         // 128 x 65
    float* vs   = ks + BH * QK_LD;         // 128 x 65
    float* Ss   = vs + BH * QK_LD;         // 128 x 129
    float* invq = Ss + BH * S_LD;          // 128
    float* invk = invq + BH;               // 128

    const int t = blockIdx.x;
    const int tid = threadIdx.x;

    for (int idx = tid; idx < BH * (HDIM / 4); idx += 256) {
        int a  = idx >> 4;
        int d4 = (idx & 15) << 2;
        int b = a >> 4, h = a & 15;
        const float* base = g_qkv + (size_t)(t * BATCH + b) * NQKV + h * HDIM + d4;
        float4 qv = *(const float4*)(base);
        float4 kv = *(const float4*)(base + EMBED);
        float4 vv = *(const float4*)(base + 2 * EMBED);
        float* qd = qs + a * QK_LD + d4;
        qd[0] = qv.x; qd[1] = qv.y; qd[2] = qv.z; qd[3] = qv.w;
        float* kd = ks + a * QK_LD + d4;
        kd[0] = kv.x; kd[1] = kv.y; kd[2] = kv.z; kd[3] = kv.w;
        float* vd = vs + a * QK_LD + d4;
        vd[0] = vv.x; vd[1] = vv.y; vd[2] = vv.z; vd[3] = vv.w;
    }
    __syncthreads();

    if (tid < BH) {
        const float* r = qs + tid * QK_LD;
        float s = 0.0f;
#pragma unroll
        for (int d = 0; d < HDIM; d++) s = fmaf(r[d], r[d], s);
        invq[tid] = rsqrtf(s);
    } else {
        const float* r = ks + (tid - BH) * QK_LD;
        float s = 0.0f;
#pragma unroll
        for (int d = 0; d < HDIM; d++) s = fmaf(r[d], r[d], s);
        invk[tid - BH] = rsqrtf(s);
    }
    __syncthreads();

    const int tx = tid & 15, ty = tid >> 4;

    {
        float acc[8][8];
#pragma unroll
        for (int i = 0; i < 8; i++)
#pragma unroll
            for (int j = 0; j < 8; j++) acc[i][j] = 0.0f;

#pragma unroll 8
        for (int k = 0; k < HDIM; k++) {
            float a_frag[8], b_frag[8];
#pragma unroll
            for (int i = 0; i < 8; i++) a_frag[i] = qs[((ty << 3) + i) * QK_LD + k];
#pragma unroll
            for (int j = 0; j < 8; j++) b_frag[j] = ks[((tx << 3) + j) * QK_LD + k];
#pragma unroll
            for (int i = 0; i < 8; i++)
#pragma unroll
                for (int j = 0; j < 8; j++)
                    acc[i][j] = fmaf(a_frag[i], b_frag[j], acc[i][j]);
        }
#pragma unroll
        for (int i = 0; i < 8; i++) {
            float si = invq[(ty << 3) + i] * 0.125f;
            float* srow = Ss + ((ty << 3) + i) * S_LD + (tx << 3);
#pragma unroll
            for (int j = 0; j < 8; j++)
                srow[j] = acc[i][j] * si * invk[(tx << 3) + j];
        }
    }
    __syncthreads();

    {
        const int warp = tid >> 5, lane = tid & 31;
        for (int r = warp * 16; r < warp * 16 + 16; r++) {
            float* row = Ss + r * S_LD;
            float v0 = row[lane], v1 = row[lane + 32];
            float v2 = row[lane + 64], v3 = row[lane + 96];
            float m = fmaxf(fmaxf(v0, v1), fmaxf(v2, v3));
#pragma unroll
            for (int o = 16; o > 0; o >>= 1)
                m = fmaxf(m, __shfl_xor_sync(0xffffffffu, m, o));
            v0 = __expf(v0 - m); v1 = __expf(v1 - m);
            v2 = __expf(v2 - m); v3 = __expf(v3 - m);
            float s = v0 + v1 + v2 + v3;
#pragma unroll
            for (int o = 16; o > 0; o >>= 1)
                s += __shfl_xor_sync(0xffffffffu, s, o);
            float inv = 1.0f / s;
            row[lane] = v0 * inv; row[lane + 32] = v1 * inv;
            row[lane + 64] = v2 * inv; row[lane + 96] = v3 * inv;
        }
    }
    __syncthreads();

    {
        float o[8][4];
#pragma unroll
        for (int i = 0; i < 8; i++)
#pragma unroll
            for (int c = 0; c < 4; c++) o[i][c] = 0.0f;

#pragma unroll 4
        for (int j = 0; j < BH; j++) {
            const float* vrow = vs + j * QK_LD + (tx << 2);
            float vv0 = vrow[0], vv1 = vrow[1], vv2 = vrow[2], vv3 = vrow[3];
#pragma unroll
            for (int i = 0; i < 8; i++) {
                float p = Ss[((ty << 3) + i) * S_LD + j];
                o[i][0] = fmaf(p, vv0, o[i][0]);
                o[i][1] = fmaf(p, vv1, o[i][1]);
                o[i][2] = fmaf(p, vv2, o[i][2]);
                o[i][3] = fmaf(p, vv3, o[i][3]);
            }
        }
#pragma unroll
        for (int i = 0; i < 8; i++) {
            int a = (ty << 3) + i;
            int b = a >> 4, h = a & 15;
            float* dst = g_ws + ((size_t)b * T_LEN + t) * EMBED + h * HDIM + (tx << 2);
            float4 ov = make_float4(o[i][0], o[i][1], o[i][2], o[i][3]);
            *(float4*)dst = ov;
        }
    }
}

__global__ __launch_bounds__(256, 1) void gemm_qkv_entry(
    const float* __restrict__ X, const float* __restrict__ W,
    const float* __restrict__ bias)
{
    // forwards to shared code path via direct call is not possible for
    // extern-shared entry; kept as thin wrappers below instead.
}

// ---------------------------------------------------------------------------
extern "C" void kernel_launch(void* const* d_in, const int* in_sizes, int n_in,
                              void* d_out, int out_size)
{
    const float* query = (const float*)d_in[0];
    // d_in[1] = key, d_in[2] = value: unused by the reference math
    const float* w_qkv = (const float*)d_in[3];
    const float* b_qkv = (const float*)d_in[4];
    const float* w_out = (const float*)d_in[5];
    const float* b_out = (const float*)d_in[6];
    float* out = (float*)d_out;

    static int configured = 0;
    const int attn_smem = (3 * BH * QK_LD + BH * S_LD + 2 * BH) * (int)sizeof(float);
    cudaFuncSetAttribute(attn_kernel,
                         cudaFuncAttributeMaxDynamicSharedMemorySize, attn_smem);
    cudaFuncSetAttribute(gemm_tf32_kernel,
                         cudaFuncAttributeMaxDynamicSharedMemorySize, GEMM_SMEM);
    (void)configured;

    float* qkv_ptr;
    float* ws_ptr;
    cudaGetSymbolAddress((void**)&qkv_ptr, g_qkv);
    cudaGetSymbolAddress((void**)&ws_ptr, g_ws);

    // QKV GEMM: [16384,1024] @ [3072,1024]^T -> g_qkv
    gemm_tf32_kernel<<<dim3(NQKV / 128, MROWS / 128), 256, GEMM_SMEM>>>(
        query, w_qkv, b_qkv, qkv_ptr, NQKV, EMBED);
    // fused per-t attention -> g_ws [B,T,E]
    attn_kernel<<<T_LEN, 256, attn_smem>>>();
    // out GEMM: [16384,1024] @ [1024,1024]^T -> out
    gemm_tf32_kernel<<<dim3(EMBED / 128, MROWS / 128), 256, GEMM_SMEM>>>(
        ws_ptr, w_out, b_out, out, EMBED, EMBED);
}

// round 5
// speedup vs baseline: 2.7586x; 1.0308x over previous
#include <cuda_runtime.h>
#include <cstdint>

#define T_LEN 2048
#define BATCH 8
#define EMBED 1024
#define NHEADS 16
#define HDIM 64
#define BH 128            // BATCH * NHEADS
#define MROWS 16384       // T_LEN * BATCH
#define NQKV 3072         // 3 * EMBED
#define QK_LD 65
#define S_LD 129

#define BK 32
#define TLD 36            // smem leading dim (floats) for A/B tiles
#define STAGES 3
#define TILE_FLOATS (128 * TLD)
#define GEMM_SMEM (STAGES * 2 * TILE_FLOATS * 4)

// Scratch (allowed: __device__ globals, no dynamic allocation)
__device__ float g_qkv[(size_t)MROWS * NQKV];    // [T*B, 3E]
__device__ float g_ws[(size_t)MROWS * EMBED];    // [B, T, E] (tf32-rounded)
__device__ float g_qr[(size_t)MROWS * EMBED];    // query, tf32-rounded
__device__ float g_wqkv[(size_t)NQKV * EMBED];   // w_qkv, tf32-rounded
__device__ float g_wout[(size_t)EMBED * EMBED];  // w_out, tf32-rounded

__device__ __forceinline__ float tf32r(float x) {
    uint32_t u;
    asm("cvt.rna.tf32.f32 %0, %1;\n" : "=r"(u) : "f"(x));
    return __uint_as_float(u);
}

// ---------------------------------------------------------------------------
// Elementwise tf32 rounding: y = round_tf32(x), float4-vectorized.
// ---------------------------------------------------------------------------
__global__ __launch_bounds__(256) void round_tf32_kernel(
    const float* __restrict__ x, float* __restrict__ y, int n4)
{
    int i = blockIdx.x * blockDim.x + threadIdx.x;
    if (i < n4) {
        float4 v = ((const float4*)x)[i];
        v.x = tf32r(v.x); v.y = tf32r(v.y);
        v.z = tf32r(v.z); v.w = tf32r(v.w);
        ((float4*)y)[i] = v;
    }
}

// ---------------------------------------------------------------------------
// tf32 tensor-core GEMM: C[m][n] = sum_k A[m][k]*B[n][k] + bias[n]
// A and B MUST already be tf32-rounded (no cvt in the mainloop).
// 128x128 tile, BK=32, 256 threads, 8 warps (2x4), warp tile 64x32.
// ldmatrix.x4.b16 for BOTH A and B fragments (b16 8x8 == fp32 8x4 with
// thread t holding fp32 (t/4, t%4) -- exactly the tf32 fragment layouts).
// ---------------------------------------------------------------------------
__global__ __launch_bounds__(256, 1) void gemm_tf32_kernel(
    const float* __restrict__ A, const float* __restrict__ B,
    const float* __restrict__ bias, float* __restrict__ C,
    int N, int K)
{
    extern __shared__ float sm[];
    const int tid  = threadIdx.x;
    const int lane = tid & 31;
    const int warp = tid >> 5;
    const int wm   = warp >> 2;        // 0..1
    const int wn   = warp & 3;         // 0..3
    const int bm   = blockIdx.y << 7;
    const int bn   = blockIdx.x << 7;

    const int lrow = tid >> 3;         // 0..31
    const int lkc  = tid & 7;          // 0..7 (float4 chunks)
    const float* gA = A + (size_t)(bm + lrow) * K + lkc * 4;
    const float* gB = B + (size_t)(bn + lrow) * K + lkc * 4;

    // Precomputed ldmatrix shared addresses (loop-invariant parts)
    // A x4: mat0 rows0-7 k0-3, mat1 rows8-15 k0-3, mat2 rows0-7 k4-7, mat3 rows8-15 k4-7
    const int a_row = wm * 64 + (lane & 15);          // + mf*16
    const int a_kof = (lane >> 4) * 4;
    // B x4: mat0 n0-7 k0-3, mat1 n0-7 k4-7, mat2 n8-15 k0-3, mat3 n8-15 k4-7
    const int b_row = wn * 32 + (lane & 7) + ((lane >> 4) << 3);  // + bi*16
    const int b_kof = ((lane >> 3) & 1) * 4;

    float c[4][4][4];
#pragma unroll
    for (int mf = 0; mf < 4; mf++)
#pragma unroll
        for (int nf = 0; nf < 4; nf++)
#pragma unroll
            for (int r = 0; r < 4; r++) c[mf][nf][r] = 0.0f;

    const int ntiles = K >> 5;

#define LOAD_TILE(s, k0) do {                                                  \
    float* As_ = sm + (s) * (2 * TILE_FLOATS);                                 \
    float* Bs_ = As_ + TILE_FLOATS;                                            \
    _Pragma("unroll")                                                          \
    for (int i_ = 0; i_ < 4; i_++) {                                           \
        uint32_t sa_ = (uint32_t)__cvta_generic_to_shared(                     \
            As_ + (lrow + i_ * 32) * TLD + lkc * 4);                           \
        asm volatile("cp.async.cg.shared.global [%0], [%1], 16;\n"             \
                     :: "r"(sa_), "l"(gA + (size_t)(i_ * 32) * K + (k0)));     \
        uint32_t sb_ = (uint32_t)__cvta_generic_to_shared(                     \
            Bs_ + (lrow + i_ * 32) * TLD + lkc * 4);                           \
        asm volatile("cp.async.cg.shared.global [%0], [%1], 16;\n"             \
                     :: "r"(sb_), "l"(gB + (size_t)(i_ * 32) * K + (k0)));     \
    }                                                                          \
} while (0)

#pragma unroll
    for (int s = 0; s < STAGES - 1; s++) {
        if (s < ntiles) LOAD_TILE(s, s * BK);
        asm volatile("cp.async.commit_group;\n");
    }
    asm volatile("cp.async.wait_group %0;\n" :: "n"(STAGES - 2));
    __syncthreads();

    for (int kt = 0; kt < ntiles; kt++) {
        int pf = kt + STAGES - 1;
        if (pf < ntiles) LOAD_TILE(pf % STAGES, pf * BK);
        asm volatile("cp.async.commit_group;\n");

        const float* As = sm + (kt % STAGES) * (2 * TILE_FLOATS);
        const float* Bs = As + TILE_FLOATS;

#pragma unroll
        for (int k8 = 0; k8 < 4; k8++) {
            uint32_t afr[4][4];
#pragma unroll
            for (int mf = 0; mf < 4; mf++) {
                uint32_t addr = (uint32_t)__cvta_generic_to_shared(
                    As + (a_row + mf * 16) * TLD + k8 * 8 + a_kof);
                asm volatile(
                    "ldmatrix.sync.aligned.m8n8.x4.b16 {%0,%1,%2,%3}, [%4];\n"
                    : "=r"(afr[mf][0]), "=r"(afr[mf][1]),
                      "=r"(afr[mf][2]), "=r"(afr[mf][3])
                    : "r"(addr));
            }
            uint32_t bfr[4][2];
#pragma unroll
            for (int bi = 0; bi < 2; bi++) {
                uint32_t addr = (uint32_t)__cvta_generic_to_shared(
                    Bs + (b_row + bi * 16) * TLD + k8 * 8 + b_kof);
                asm volatile(
                    "ldmatrix.sync.aligned.m8n8.x4.b16 {%0,%1,%2,%3}, [%4];\n"
                    : "=r"(bfr[2 * bi][0]),     "=r"(bfr[2 * bi][1]),
                      "=r"(bfr[2 * bi + 1][0]), "=r"(bfr[2 * bi + 1][1])
                    : "r"(addr));
            }
#pragma unroll
            for (int mf = 0; mf < 4; mf++)
#pragma unroll
                for (int nf = 0; nf < 4; nf++) {
                    asm volatile(
                        "mma.sync.aligned.m16n8k8.row.col.f32.tf32.tf32.f32 "
                        "{%0,%1,%2,%3}, {%4,%5,%6,%7}, {%8,%9}, {%0,%1,%2,%3};\n"
                        : "+f"(c[mf][nf][0]), "+f"(c[mf][nf][1]),
                          "+f"(c[mf][nf][2]), "+f"(c[mf][nf][3])
                        : "r"(afr[mf][0]), "r"(afr[mf][1]),
                          "r"(afr[mf][2]), "r"(afr[mf][3]),
                          "r"(bfr[nf][0]), "r"(bfr[nf][1]));
                }
        }

        asm volatile("cp.async.wait_group %0;\n" :: "n"(STAGES - 2));
        __syncthreads();
    }

    // epilogue
#pragma unroll
    for (int mf = 0; mf < 4; mf++) {
        int r0 = bm + wm * 64 + mf * 16 + (lane >> 2);
#pragma unroll
        for (int nf = 0; nf < 4; nf++) {
            int col = bn + wn * 32 + nf * 8 + ((lane & 3) << 1);
            float2 bv = *(const float2*)(bias + col);
            float2 o0 = make_float2(c[mf][nf][0] + bv.x, c[mf][nf][1] + bv.y);
            float2 o1 = make_float2(c[mf][nf][2] + bv.x, c[mf][nf][3] + bv.y);
            *(float2*)(C + (size_t)r0 * N + col) = o0;
            *(float2*)(C + (size_t)(r0 + 8) * N + col) = o1;
        }
    }
#undef LOAD_TILE
}

// ---------------------------------------------------------------------------
// Per-t attention: one block per t (2048 blocks, 256 threads). fp32 exact.
// S[i][j] = (q_raw[i].k_raw[j]) * invq[i] * invk[j] / 8, softmax, P@V.
// Output is tf32-rounded at store (consumed by the tf32 out-GEMM).
// ---------------------------------------------------------------------------
__global__ __launch_bounds__(256) void attn_kernel()
{
    extern __shared__ float smem[];
    float* qs   = smem;                    // 128 x 65
    float* ks   = qs + BH * QK_LD;         // 128 x 65
    float* vs   = ks + BH * QK_LD;         // 128 x 65
    float* Ss   = vs + BH * QK_LD;         // 128 x 129
    float* invq = Ss + BH * S_LD;          // 128
    float* invk = invq + BH;               // 128

    const int t = blockIdx.x;
    const int tid = threadIdx.x;

    for (int idx = tid; idx < BH * (HDIM / 4); idx += 256) {
        int a  = idx >> 4;
        int d4 = (idx & 15) << 2;
        int b = a >> 4, h = a & 15;
        const float* base = g_qkv + (size_t)(t * BATCH + b) * NQKV + h * HDIM + d4;
        float4 qv = *(const float4*)(base);
        float4 kv = *(const float4*)(base + EMBED);
        float4 vv = *(const float4*)(base + 2 * EMBED);
        float* qd = qs + a * QK_LD + d4;
        qd[0] = qv.x; qd[1] = qv.y; qd[2] = qv.z; qd[3] = qv.w;
        float* kd = ks + a * QK_LD + d4;
        kd[0] = kv.x; kd[1] = kv.y; kd[2] = kv.z; kd[3] = kv.w;
        float* vd = vs + a * QK_LD + d4;
        vd[0] = vv.x; vd[1] = vv.y; vd[2] = vv.z; vd[3] = vv.w;
    }
    __syncthreads();

    if (tid < BH) {
        const float* r = qs + tid * QK_LD;
        float s = 0.0f;
#pragma unroll
        for (int d = 0; d < HDIM; d++) s = fmaf(r[d], r[d], s);
        invq[tid] = rsqrtf(s);
    } else {
        const float* r = ks + (tid - BH) * QK_LD;
        float s = 0.0f;
#pragma unroll
        for (int d = 0; d < HDIM; d++) s = fmaf(r[d], r[d], s);
        invk[tid - BH] = rsqrtf(s);
    }
    __syncthreads();

    const int tx = tid & 15, ty = tid >> 4;

    {
        float acc[8][8];
#pragma unroll
        for (int i = 0; i < 8; i++)
#pragma unroll
            for (int j = 0; j < 8; j++) acc[i][j] = 0.0f;

#pragma unroll 8
        for (int k = 0; k < HDIM; k++) {
            float a_frag[8], b_frag[8];
#pragma unroll
            for (int i = 0; i < 8; i++) a_frag[i] = qs[((ty << 3) + i) * QK_LD + k];
#pragma unroll
            for (int j = 0; j < 8; j++) b_frag[j] = ks[((tx << 3) + j) * QK_LD + k];
#pragma unroll
            for (int i = 0; i < 8; i++)
#pragma unroll
                for (int j = 0; j < 8; j++)
                    acc[i][j] = fmaf(a_frag[i], b_frag[j], acc[i][j]);
        }
#pragma unroll
        for (int i = 0; i < 8; i++) {
            float si = invq[(ty << 3) + i] * 0.125f;
            float* srow = Ss + ((ty << 3) + i) * S_LD + (tx << 3);
#pragma unroll
            for (int j = 0; j < 8; j++)
                srow[j] = acc[i][j] * si * invk[(tx << 3) + j];
        }
    }
    __syncthreads();

    {
        const int warp = tid >> 5, lane = tid & 31;
        for (int r = warp * 16; r < warp * 16 + 16; r++) {
            float* row = Ss + r * S_LD;
            float v0 = row[lane], v1 = row[lane + 32];
            float v2 = row[lane + 64], v3 = row[lane + 96];
            float m = fmaxf(fmaxf(v0, v1), fmaxf(v2, v3));
#pragma unroll
            for (int o = 16; o > 0; o >>= 1)
                m = fmaxf(m, __shfl_xor_sync(0xffffffffu, m, o));
            v0 = __expf(v0 - m); v1 = __expf(v1 - m);
            v2 = __expf(v2 - m); v3 = __expf(v3 - m);
            float s = v0 + v1 + v2 + v3;
#pragma unroll
            for (int o = 16; o > 0; o >>= 1)
                s += __shfl_xor_sync(0xffffffffu, s, o);
            float inv = 1.0f / s;
            row[lane] = v0 * inv; row[lane + 32] = v1 * inv;
            row[lane + 64] = v2 * inv; row[lane + 96] = v3 * inv;
        }
    }
    __syncthreads();

    {
        float o[8][4];
#pragma unroll
        for (int i = 0; i < 8; i++)
#pragma unroll
            for (int c = 0; c < 4; c++) o[i][c] = 0.0f;

#pragma unroll 4
        for (int j = 0; j < BH; j++) {
            const float* vrow = vs + j * QK_LD + (tx << 2);
            float vv0 = vrow[0], vv1 = vrow[1], vv2 = vrow[2], vv3 = vrow[3];
#pragma unroll
            for (int i = 0; i < 8; i++) {
                float p = Ss[((ty << 3) + i) * S_LD + j];
                o[i][0] = fmaf(p, vv0, o[i][0]);
                o[i][1] = fmaf(p, vv1, o[i][1]);
                o[i][2] = fmaf(p, vv2, o[i][2]);
                o[i][3] = fmaf(p, vv3, o[i][3]);
            }
        }
#pragma unroll
        for (int i = 0; i < 8; i++) {
            int a = (ty << 3) + i;
            int b = a >> 4, h = a & 15;
            float* dst = g_ws + ((size_t)b * T_LEN + t) * EMBED + h * HDIM + (tx << 2);
            float4 ov = make_float4(tf32r(o[i][0]), tf32r(o[i][1]),
                                    tf32r(o[i][2]), tf32r(o[i][3]));
            *(float4*)dst = ov;
        }
    }
}

// ---------------------------------------------------------------------------
extern "C" void kernel_launch(void* const* d_in, const int* in_sizes, int n_in,
                              void* d_out, int out_size)
{
    const float* query = (const float*)d_in[0];
    // d_in[1] = key, d_in[2] = value: unused by the reference math
    const float* w_qkv = (const float*)d_in[3];
    const float* b_qkv = (const float*)d_in[4];
    const float* w_out = (const float*)d_in[5];
    const float* b_out = (const float*)d_in[6];
    float* out = (float*)d_out;

    const int attn_smem = (3 * BH * QK_LD + BH * S_LD + 2 * BH) * (int)sizeof(float);
    cudaFuncSetAttribute(attn_kernel,
                         cudaFuncAttributeMaxDynamicSharedMemorySize, attn_smem);
    cudaFuncSetAttribute(gemm_tf32_kernel,
                         cudaFuncAttributeMaxDynamicSharedMemorySize, GEMM_SMEM);

    float *qkv_ptr, *ws_ptr, *qr_ptr, *wqkv_ptr, *wout_ptr;
    cudaGetSymbolAddress((void**)&qkv_ptr, g_qkv);
    cudaGetSymbolAddress((void**)&ws_ptr, g_ws);
    cudaGetSymbolAddress((void**)&qr_ptr, g_qr);
    cudaGetSymbolAddress((void**)&wqkv_ptr, g_wqkv);
    cudaGetSymbolAddress((void**)&wout_ptr, g_wout);

    // Pre-round all tf32 GEMM operands (round-to-nearest-even on 19-bit tf32).
    {
        int n4q = (MROWS * EMBED) / 4;
        round_tf32_kernel<<<(n4q + 255) / 256, 256>>>(query, qr_ptr, n4q);
        int n4w = (NQKV * EMBED) / 4;
        round_tf32_kernel<<<(n4w + 255) / 256, 256>>>(w_qkv, wqkv_ptr, n4w);
        int n4o = (EMBED * EMBED) / 4;
        round_tf32_kernel<<<(n4o + 255) / 256, 256>>>(w_out, wout_ptr, n4o);
    }

    // QKV GEMM: [16384,1024] @ [3072,1024]^T -> g_qkv
    gemm_tf32_kernel<<<dim3(NQKV / 128, MROWS / 128), 256, GEMM_SMEM>>>(
        qr_ptr, wqkv_ptr, b_qkv, qkv_ptr, NQKV, EMBED);
    // fused per-t attention -> g_ws [B,T,E] (tf32-rounded)
    attn_kernel<<<T_LEN, 256, attn_smem>>>();
    // out GEMM: [16384,1024] @ [1024,1024]^T -> out
    gemm_tf32_kernel<<<dim3(EMBED / 128, MROWS / 128), 256, GEMM_SMEM>>>(
        ws_ptr, wout_ptr, b_out, out, EMBED, EMBED);
}

// round 7
// speedup vs baseline: 3.0794x; 1.1163x over previous
#include <cuda_runtime.h>
#include <cstdint>

#define T_LEN 2048
#define BATCH 8
#define EMBED 1024
#define NHEADS 16
#define HDIM 64
#define BH 128            // BATCH * NHEADS
#define MROWS 16384       // T_LEN * BATCH
#define NQKV 3072         // 3 * EMBED
#define QK_LD 65
#define S_LD 129

#define BK 32
#define TLD 36            // smem leading dim (floats) for A/B tiles
#define STAGES 2
#define TILE_FLOATS (128 * TLD)
#define GEMM_SMEM (STAGES * 2 * TILE_FLOATS * 4)   // 73728 B -> 2 CTAs/SM

// Scratch (allowed: __device__ globals, no dynamic allocation)
__device__ float g_qkv[(size_t)MROWS * NQKV];    // [T*B, 3E]
__device__ float g_ws[(size_t)MROWS * EMBED];    // [B, T, E] (tf32-rounded)
__device__ float g_qr[(size_t)MROWS * EMBED];    // query, tf32-rounded
__device__ float g_wqkv[(size_t)NQKV * EMBED];   // w_qkv, tf32-rounded
__device__ float g_wout[(size_t)EMBED * EMBED];  // w_out, tf32-rounded

__device__ __forceinline__ float tf32r(float x) {
    uint32_t u;
    asm("cvt.rna.tf32.f32 %0, %1;\n" : "=r"(u) : "f"(x));
    return __uint_as_float(u);
}

// ---------------------------------------------------------------------------
// Elementwise tf32 rounding: y = round_tf32(x), float4-vectorized.
// ---------------------------------------------------------------------------
__global__ __launch_bounds__(256) void round_tf32_kernel(
    const float* __restrict__ x, float* __restrict__ y, int n4)
{
    int i = blockIdx.x * blockDim.x + threadIdx.x;
    if (i < n4) {
        float4 v = ((const float4*)x)[i];
        v.x = tf32r(v.x); v.y = tf32r(v.y);
        v.z = tf32r(v.z); v.w = tf32r(v.w);
        ((float4*)y)[i] = v;
    }
}

// ---------------------------------------------------------------------------
// tf32 tensor-core GEMM: C[m][n] = sum_k A[m][k]*B[n][k] + bias[n]
// A and B MUST already be tf32-rounded (no cvt in the mainloop).
// 128x128 tile, BK=32, 256 threads, 8 warps (2x4), warp tile 64x32.
// 2-stage cp.async double-buffer; __launch_bounds__(256,2) caps regs at 128
// so 2 CTAs co-reside per SM (smem 73.7KB x2 fits) -> 4 warps/SMSP.
// ldmatrix.x4.b16 for BOTH A and B fragments.
// ---------------------------------------------------------------------------
__global__ __launch_bounds__(256, 2) void gemm_tf32_kernel(
    const float* __restrict__ A, const float* __restrict__ B,
    const float* __restrict__ bias, float* __restrict__ C,
    int N, int K)
{
    extern __shared__ float sm[];
    const int tid  = threadIdx.x;
    const int lane = tid & 31;
    const int warp = tid >> 5;
    const int wm   = warp >> 2;        // 0..1
    const int wn   = warp & 3;         // 0..3
    const int bm   = blockIdx.y << 7;
    const int bn   = blockIdx.x << 7;

    const int lrow = tid >> 3;         // 0..31
    const int lkc  = tid & 7;          // 0..7 (float4 chunks)
    const float* gA = A + (size_t)(bm + lrow) * K + lkc * 4;
    const float* gB = B + (size_t)(bn + lrow) * K + lkc * 4;

    // Precomputed ldmatrix shared coords (loop-invariant parts)
    const int a_row = wm * 64 + (lane & 15);          // + mf*16
    const int a_kof = (lane >> 4) * 4;
    const int b_row = wn * 32 + (lane & 7) + ((lane >> 4) << 3);  // + bi*16
    const int b_kof = ((lane >> 3) & 1) * 4;

    float c[4][4][4];
#pragma unroll
    for (int mf = 0; mf < 4; mf++)
#pragma unroll
        for (int nf = 0; nf < 4; nf++)
#pragma unroll
            for (int r = 0; r < 4; r++) c[mf][nf][r] = 0.0f;

    const int ntiles = K >> 5;

#define LOAD_TILE(s, k0) do {                                                  \
    float* As_ = sm + (s) * (2 * TILE_FLOATS);                                 \
    float* Bs_ = As_ + TILE_FLOATS;                                            \
    _Pragma("unroll")                                                          \
    for (int i_ = 0; i_ < 4; i_++) {                                           \
        uint32_t sa_ = (uint32_t)__cvta_generic_to_shared(                     \
            As_ + (lrow + i_ * 32) * TLD + lkc * 4);                           \
        asm volatile("cp.async.cg.shared.global [%0], [%1], 16;\n"             \
                     :: "r"(sa_), "l"(gA + (size_t)(i_ * 32) * K + (k0)));     \
        uint32_t sb_ = (uint32_t)__cvta_generic_to_shared(                     \
            Bs_ + (lrow + i_ * 32) * TLD + lkc * 4);                           \
        asm volatile("cp.async.cg.shared.global [%0], [%1], 16;\n"             \
                     :: "r"(sb_), "l"(gB + (size_t)(i_ * 32) * K + (k0)));     \
    }                                                                          \
} while (0)

    // prologue: fill stage 0
    LOAD_TILE(0, 0);
    asm volatile("cp.async.commit_group;\n");
    asm volatile("cp.async.wait_group 0;\n");
    __syncthreads();

    for (int kt = 0; kt < ntiles; kt++) {
        // prefetch next tile into the other stage; overlaps this tile's mma
        int pf = kt + 1;
        if (pf < ntiles) LOAD_TILE(pf & 1, pf * BK);
        asm volatile("cp.async.commit_group;\n");

        const float* As = sm + (kt & 1) * (2 * TILE_FLOATS);
        const float* Bs = As + TILE_FLOATS;

#pragma unroll
        for (int k8 = 0; k8 < 4; k8++) {
            uint32_t afr[4][4];
#pragma unroll
            for (int mf = 0; mf < 4; mf++) {
                uint32_t addr = (uint32_t)__cvta_generic_to_shared(
                    As + (a_row + mf * 16) * TLD + k8 * 8 + a_kof);
                asm volatile(
                    "ldmatrix.sync.aligned.m8n8.x4.b16 {%0,%1,%2,%3}, [%4];\n"
                    : "=r"(afr[mf][0]), "=r"(afr[mf][1]),
                      "=r"(afr[mf][2]), "=r"(afr[mf][3])
                    : "r"(addr));
            }
            uint32_t bfr[4][2];
#pragma unroll
            for (int bi = 0; bi < 2; bi++) {
                uint32_t addr = (uint32_t)__cvta_generic_to_shared(
                    Bs + (b_row + bi * 16) * TLD + k8 * 8 + b_kof);
                asm volatile(
                    "ldmatrix.sync.aligned.m8n8.x4.b16 {%0,%1,%2,%3}, [%4];\n"
                    : "=r"(bfr[2 * bi][0]),     "=r"(bfr[2 * bi][1]),
                      "=r"(bfr[2 * bi + 1][0]), "=r"(bfr[2 * bi + 1][1])
                    : "r"(addr));
            }
#pragma unroll
            for (int mf = 0; mf < 4; mf++)
#pragma unroll
                for (int nf = 0; nf < 4; nf++) {
                    asm volatile(
                        "mma.sync.aligned.m16n8k8.row.col.f32.tf32.tf32.f32 "
                        "{%0,%1,%2,%3}, {%4,%5,%6,%7}, {%8,%9}, {%0,%1,%2,%3};\n"
                        : "+f"(c[mf][nf][0]), "+f"(c[mf][nf][1]),
                          "+f"(c[mf][nf][2]), "+f"(c[mf][nf][3])
                        : "r"(afr[mf][0]), "r"(afr[mf][1]),
                          "r"(afr[mf][2]), "r"(afr[mf][3]),
                          "r"(bfr[nf][0]), "r"(bfr[nf][1]));
                }
        }

        asm volatile("cp.async.wait_group 0;\n");
        __syncthreads();
    }

    // epilogue
#pragma unroll
    for (int mf = 0; mf < 4; mf++) {
        int r0 = bm + wm * 64 + mf * 16 + (lane >> 2);
#pragma unroll
        for (int nf = 0; nf < 4; nf++) {
            int col = bn + wn * 32 + nf * 8 + ((lane & 3) << 1);
            float2 bv = *(const float2*)(bias + col);
            float2 o0 = make_float2(c[mf][nf][0] + bv.x, c[mf][nf][1] + bv.y);
            float2 o1 = make_float2(c[mf][nf][2] + bv.x, c[mf][nf][3] + bv.y);
            *(float2*)(C + (size_t)r0 * N + col) = o0;
            *(float2*)(C + (size_t)(r0 + 8) * N + col) = o1;
        }
    }
#undef LOAD_TILE
}

// ---------------------------------------------------------------------------
// Per-t attention: one block per t (2048 blocks, 256 threads). fp32 exact.
// S[i][j] = (q_raw[i].k_raw[j]) * invq[i] * invk[j] / 8, softmax, P@V.
// Output tf32-rounded at store (consumed by the tf32 out-GEMM).
// ---------------------------------------------------------------------------
__global__ __launch_bounds__(256) void attn_kernel()
{
    extern __shared__ float fsm[];
    float* qs   = fsm;                     // 128 x 65
    float* ks   = qs + BH * QK_LD;         // 128 x 65
    float* vs   = ks + BH * QK_LD;         // 128 x 65
    float* Ss   = vs + BH * QK_LD;         // 128 x 129
    float* invq = Ss + BH * S_LD;          // 128
    float* invk = invq + BH;               // 128

    const int t = blockIdx.x;
    const int tid = threadIdx.x;

    for (int idx = tid; idx < BH * (HDIM / 4); idx += 256) {
        int a  = idx >> 4;
        int d4 = (idx & 15) << 2;
        int b = a >> 4, h = a & 15;
        const float* base = g_qkv + (size_t)(t * BATCH + b) * NQKV + h * HDIM + d4;
        float4 qv = *(const float4*)(base);
        float4 kv = *(const float4*)(base + EMBED);
        float4 vv = *(const float4*)(base + 2 * EMBED);
        float* qd = qs + a * QK_LD + d4;
        qd[0] = qv.x; qd[1] = qv.y; qd[2] = qv.z; qd[3] = qv.w;
        float* kd = ks + a * QK_LD + d4;
        kd[0] = kv.x; kd[1] = kv.y; kd[2] = kv.z; kd[3] = kv.w;
        float* vd = vs + a * QK_LD + d4;
        vd[0] = vv.x; vd[1] = vv.y; vd[2] = vv.z; vd[3] = vv.w;
    }
    __syncthreads();

    if (tid < BH) {
        const float* r = qs + tid * QK_LD;
        float s = 0.0f;
#pragma unroll
        for (int d = 0; d < HDIM; d++) s = fmaf(r[d], r[d], s);
        invq[tid] = rsqrtf(s);
    } else {
        const float* r = ks + (tid - BH) * QK_LD;
        float s = 0.0f;
#pragma unroll
        for (int d = 0; d < HDIM; d++) s = fmaf(r[d], r[d], s);
        invk[tid - BH] = rsqrtf(s);
    }
    __syncthreads();

    const int tx = tid & 15, ty = tid >> 4;

    {
        float acc[8][8];
#pragma unroll
        for (int i = 0; i < 8; i++)
#pragma unroll
            for (int j = 0; j < 8; j++) acc[i][j] = 0.0f;

#pragma unroll 8
        for (int k = 0; k < HDIM; k++) {
            float a_frag[8], b_frag[8];
#pragma unroll
            for (int i = 0; i < 8; i++) a_frag[i] = qs[((ty << 3) + i) * QK_LD + k];
#pragma unroll
            for (int j = 0; j < 8; j++) b_frag[j] = ks[((tx << 3) + j) * QK_LD + k];
#pragma unroll
            for (int i = 0; i < 8; i++)
#pragma unroll
                for (int j = 0; j < 8; j++)
                    acc[i][j] = fmaf(a_frag[i], b_frag[j], acc[i][j]);
        }
#pragma unroll
        for (int i = 0; i < 8; i++) {
            float si = invq[(ty << 3) + i] * 0.125f;
            float* srow = Ss + ((ty << 3) + i) * S_LD + (tx << 3);
#pragma unroll
            for (int j = 0; j < 8; j++)
                srow[j] = acc[i][j] * si * invk[(tx << 3) + j];
        }
    }
    __syncthreads();

    {
        const int warp = tid >> 5, lane = tid & 31;
        for (int r = warp * 16; r < warp * 16 + 16; r++) {
            float* row = Ss + r * S_LD;
            float v0 = row[lane], v1 = row[lane + 32];
            float v2 = row[lane + 64], v3 = row[lane + 96];
            float m = fmaxf(fmaxf(v0, v1), fmaxf(v2, v3));
#pragma unroll
            for (int o = 16; o > 0; o >>= 1)
                m = fmaxf(m, __shfl_xor_sync(0xffffffffu, m, o));
            v0 = __expf(v0 - m); v1 = __expf(v1 - m);
            v2 = __expf(v2 - m); v3 = __expf(v3 - m);
            float s = v0 + v1 + v2 + v3;
#pragma unroll
            for (int o = 16; o > 0; o >>= 1)
                s += __shfl_xor_sync(0xffffffffu, s, o);
            float inv = 1.0f / s;
            row[lane] = v0 * inv; row[lane + 32] = v1 * inv;
            row[lane + 64] = v2 * inv; row[lane + 96] = v3 * inv;
        }
    }
    __syncthreads();

    {
        float o[8][4];
#pragma unroll
        for (int i = 0; i < 8; i++)
#pragma unroll
            for (int c = 0; c < 4; c++) o[i][c] = 0.0f;

#pragma unroll 4
        for (int j = 0; j < BH; j++) {
            const float* vrow = vs + j * QK_LD + (tx << 2);
            float vv0 = vrow[0], vv1 = vrow[1], vv2 = vrow[2], vv3 = vrow[3];
#pragma unroll
            for (int i = 0; i < 8; i++) {
                float p = Ss[((ty << 3) + i) * S_LD + j];
                o[i][0] = fmaf(p, vv0, o[i][0]);
                o[i][1] = fmaf(p, vv1, o[i][1]);
                o[i][2] = fmaf(p, vv2, o[i][2]);
                o[i][3] = fmaf(p, vv3, o[i][3]);
            }
        }
#pragma unroll
        for (int i = 0; i < 8; i++) {
            int a = (ty << 3) + i;
            int b = a >> 4, h = a & 15;
            float* dst = g_ws + ((size_t)b * T_LEN + t) * EMBED + h * HDIM + (tx << 2);
            float4 ov = make_float4(tf32r(o[i][0]), tf32r(o[i][1]),
                                    tf32r(o[i][2]), tf32r(o[i][3]));
            *(float4*)dst = ov;
        }
    }
}

// ---------------------------------------------------------------------------
extern "C" void kernel_launch(void* const* d_in, const int* in_sizes, int n_in,
                              void* d_out, int out_size)
{
    const float* query = (const float*)d_in[0];
    // d_in[1] = key, d_in[2] = value: unused by the reference math
    const float* w_qkv = (const float*)d_in[3];
    const float* b_qkv = (const float*)d_in[4];
    const float* w_out = (const float*)d_in[5];
    const float* b_out = (const float*)d_in[6];
    float* out = (float*)d_out;

    const int attn_smem = (3 * BH * QK_LD + BH * S_LD + 2 * BH) * (int)sizeof(float);
    cudaFuncSetAttribute(attn_kernel,
                         cudaFuncAttributeMaxDynamicSharedMemorySize, attn_smem);
    cudaFuncSetAttribute(gemm_tf32_kernel,
                         cudaFuncAttributeMaxDynamicSharedMemorySize, GEMM_SMEM);

    float *qkv_ptr, *ws_ptr, *qr_ptr, *wqkv_ptr, *wout_ptr;
    cudaGetSymbolAddress((void**)&qkv_ptr, g_qkv);
    cudaGetSymbolAddress((void**)&ws_ptr, g_ws);
    cudaGetSymbolAddress((void**)&qr_ptr, g_qr);
    cudaGetSymbolAddress((void**)&wqkv_ptr, g_wqkv);
    cudaGetSymbolAddress((void**)&wout_ptr, g_wout);

    // Pre-round all tf32 GEMM operands (round-to-nearest on 19-bit tf32).
    {
        int n4q = (MROWS * EMBED) / 4;
        round_tf32_kernel<<<(n4q + 255) / 256, 256>>>(query, qr_ptr, n4q);
        int n4w = (NQKV * EMBED) / 4;
        round_tf32_kernel<<<(n4w + 255) / 256, 256>>>(w_qkv, wqkv_ptr, n4w);
        int n4o = (EMBED * EMBED) / 4;
        round_tf32_kernel<<<(n4o + 255) / 256, 256>>>(w_out, wout_ptr, n4o);
    }

    // QKV GEMM: [16384,1024] @ [3072,1024]^T -> g_qkv
    gemm_tf32_kernel<<<dim3(NQKV / 128, MROWS / 128), 256, GEMM_SMEM>>>(
        qr_ptr, wqkv_ptr, b_qkv, qkv_ptr, NQKV, EMBED);
    // fused per-t attention -> g_ws [B,T,E] (tf32-rounded)
    attn_kernel<<<T_LEN, 256, attn_smem>>>();
    // out GEMM: [16384,1024] @ [1024,1024]^T -> out
    gemm_tf32_kernel<<<dim3(EMBED / 128, MROWS / 128), 256, GEMM_SMEM>>>(
        ws_ptr, wout_ptr, b_out, out, EMBED, EMBED);
}